// round 16
// baseline (speedup 1.0000x reference)
#include <cuda_runtime.h>
#include <cuda_bf16.h>
#include <cuda_fp16.h>
#include <cstdint>

#define B_    16
#define L_    512
#define HID_  1024
#define NH_   16
#define HD_   64
#define M_TOT (B_*L_)      // 8192
#define DCAT  192
#define XN    ((size_t)M_TOT*HID_)
#define WN    ((size_t)HID_*HID_)

// ---------------- scratch (static device arrays) ----------------
__device__ __half g_xf[5ULL*XN];            // fp16 activations: 4 inputs + attn-out
__device__ __half g_wfh[8ULL*WN];           // W^T fp16
__device__ __half g_qf [(size_t)B_*NH_*L_*DCAT];   // Q fp16
__device__ __half g_kf [(size_t)B_*NH_*L_*DCAT];   // K fp16
__device__ __half g_vf [(size_t)B_*NH_*HD_*L_];    // Vt fp16

// ---------------- PTX helpers (baseline ISA only) ----------------
__device__ __forceinline__ uint32_t smem_u32(const void* p) {
    uint32_t a;
    asm("{ .reg .u64 t; cvta.to.shared.u64 t, %1; cvt.u32.u64 %0, t; }" : "=r"(a) : "l"(p));
    return a;
}
__device__ __forceinline__ void cp16(uint32_t dst, const void* src) {
    asm volatile("cp.async.cg.shared.global [%0], [%1], 16;" :: "r"(dst), "l"(src));
}
__device__ __forceinline__ void ldm_x4(uint32_t* r, uint32_t addr) {
    asm volatile("ldmatrix.sync.aligned.m8n8.x4.shared.b16 {%0,%1,%2,%3}, [%4];"
                 : "=r"(r[0]), "=r"(r[1]), "=r"(r[2]), "=r"(r[3]) : "r"(addr));
}
__device__ __forceinline__ void mma16816h(float* d, const uint32_t* a, const uint32_t* b) {
    asm volatile(
        "mma.sync.aligned.m16n8k16.row.col.f32.f16.f16.f32 "
        "{%0,%1,%2,%3}, {%4,%5,%6,%7}, {%8,%9}, {%0,%1,%2,%3};"
        : "+f"(d[0]), "+f"(d[1]), "+f"(d[2]), "+f"(d[3])
        : "r"(a[0]), "r"(a[1]), "r"(a[2]), "r"(a[3]), "r"(b[0]), "r"(b[1]));
}
__device__ __forceinline__ uint32_t pack_h2(float a, float b) {
    __half2 t = __floats2half2_rn(a, b);
    return *(uint32_t*)&t;
}

// ---------------- batched fp32 -> fp16 ----------------
struct SplitSrc { const float* p[4]; };
__global__ __launch_bounds__(256)
void split_f16(SplitSrc s, __half* __restrict__ dst, int n4)
{
    int i = blockIdx.x * 256 + threadIdx.x;
    if (i >= n4) return;
    int z = blockIdx.y;
    const float* src = s.p[z];
    __half* dz = dst + (size_t)z * XN;
    float4 v = ((const float4*)src)[i];
    __half2 a = __floats2half2_rn(v.x, v.y);
    __half2 b = __floats2half2_rn(v.z, v.w);
    ((__half2*)dz)[i*2]   = a;
    ((__half2*)dz)[i*2+1] = b;
}

// ---------------- batched W[k][n] -> W^T[n][k] fp16 ----------------
struct WSrc { const float* p[8]; };
__global__ __launch_bounds__(256)
void splitT_h(WSrc s, __half* __restrict__ hiT)
{
    __shared__ float t[32][33];
    int z = blockIdx.z;
    const float* W = s.p[z];
    __half* hz = hiT + (size_t)z * WN;
    int bx = blockIdx.x * 32, by = blockIdx.y * 32;
    int tx = threadIdx.x, ty = threadIdx.y;
#pragma unroll
    for (int j = 0; j < 4; j++)
        t[ty + 8*j][tx] = W[(size_t)(by + ty + 8*j) * HID_ + bx + tx];
    __syncthreads();
#pragma unroll
    for (int j = 0; j < 4; j++) {
        float v = t[tx][ty + 8*j];
        int n = bx + ty + 8*j, k = by + tx;
        hz[(size_t)n * HID_ + k] = __float2half(v);
    }
}

// ---------------- shared GEMM constants ----------------
#define KC        64
#define NCHUNKW   16
#define ROWB      144u
#define ATILE_B   (128u*ROWB)            // 18432
#define STAGE_B   (2u*ATILE_B)           // 36864 (A + B)
#define GEMM_SMEM (3*STAGE_B)            // 110592 -> occ 2

// ---- load tile, 128-thread version (16 cp16/thread) ----
__device__ __forceinline__ void load_tile_128(
    uint32_t sbase, int stage, int c, int m0, int n0, int tid,
    const __half* A, const __half* Bh)
{
    const int k0 = c * KC;
    const uint32_t dstA = sbase + (uint32_t)stage * STAGE_B;
#pragma unroll
    for (int i = 0; i < 16; i++) {
        int idx = i * 128 + tid;                 // 0..2047
        int r = (idx >> 3) & 127, c16 = idx & 7;
        if (idx < 1024)
            cp16(dstA + r * ROWB + c16 * 16,
                 A + (size_t)(m0 + r) * HID_ + k0 + c16 * 8);
        else
            cp16(dstA + ATILE_B + r * ROWB + c16 * 16,
                 Bh + (size_t)(n0 + r) * HID_ + k0 + c16 * 8);
    }
    asm volatile("cp.async.commit_group;");
}

// ---- load tile, 256-thread version (8 cp16/thread) ----
__device__ __forceinline__ void load_tile_256(
    uint32_t sbase, int stage, int c, int m0, int n0, int tid,
    const __half* A, const __half* Bh)
{
    const int k0 = c * KC;
    const uint32_t dstA = sbase + (uint32_t)stage * STAGE_B;
#pragma unroll
    for (int i = 0; i < 8; i++) {
        int idx = i * 256 + tid;
        int r = (idx >> 3) & 127, c16 = idx & 7;
        if (idx < 1024)
            cp16(dstA + r * ROWB + c16 * 16,
                 A + (size_t)(m0 + r) * HID_ + k0 + c16 * 8);
        else
            cp16(dstA + ATILE_B + r * ROWB + c16 * 16,
                 Bh + (size_t)(n0 + r) * HID_ + k0 + c16 * 8);
    }
    asm volatile("cp.async.commit_group;");
}

// ---------------- batched projection GEMMs: 128 threads, warp 64x64 ----------------
// mode 0: scatter [bh][l][192] (Q and K); mode 2: V transpose [bh][d][l]
struct GemmB {
    const __half *A[7], *Bh[7];
    const float* bias[7];
    __half *Oh[7];
    int mode[7];
    int part[7];
};

__global__ __launch_bounds__(128, 2)
void gemm_batch(GemmB args)
{
    extern __shared__ char smem[];
    const uint32_t sbase = smem_u32(smem);
    const int z = blockIdx.z;
    const int tid = threadIdx.x;
    const int wid = tid >> 5, lane = tid & 31;
    const int m0 = blockIdx.y * 128, n0 = blockIdx.x * 128;
    const int wm = wid & 1, wn = wid >> 1;       // warp tile 64x64

    const __half* A  = args.A[z];
    const __half* Bh = args.Bh[z];

    float acc[4][8][4];
#pragma unroll
    for (int mf = 0; mf < 4; mf++)
#pragma unroll
        for (int nf = 0; nf < 8; nf++)
#pragma unroll
            for (int q = 0; q < 4; q++) acc[mf][nf][q] = 0.f;

    const uint32_t a_l = (uint32_t)(wm * 64 + (lane & 7) + ((lane >> 3) & 1) * 8) * ROWB
                       + (lane >> 4) * 16;
    const uint32_t b_l = (uint32_t)(wn * 64 + (lane & 7) + ((lane >> 4) & 1) * 8) * ROWB
                       + ((lane >> 3) & 1) * 16;

    load_tile_128(sbase, 0, 0, m0, n0, tid, A, Bh);
    load_tile_128(sbase, 1, 1, m0, n0, tid, A, Bh);

    for (int c = 0; c < NCHUNKW; c++) {
        if (c < NCHUNKW - 1) asm volatile("cp.async.wait_group 1;" ::: "memory");
        else                 asm volatile("cp.async.wait_group 0;" ::: "memory");
        __syncthreads();
        if (c + 2 < NCHUNKW)
            load_tile_128(sbase, (c + 2) % 3, c + 2, m0, n0, tid, A, Bh);

        const uint32_t sb = sbase + (uint32_t)(c % 3) * STAGE_B;
        const uint32_t aBase  = sb + a_l;
        const uint32_t bhBase = sb + ATILE_B + b_l;
#pragma unroll
        for (int kk = 0; kk < KC / 16; kk++) {
            const uint32_t koff = kk * 32;
            uint32_t aq[4][4];
#pragma unroll
            for (int mf = 0; mf < 4; mf++)
                ldm_x4(aq[mf], aBase + mf * 16 * ROWB + koff);
            uint32_t bq[16];
#pragma unroll
            for (int np = 0; np < 4; np++)
                ldm_x4(&bq[np * 4], bhBase + np * 16 * ROWB + koff);
#pragma unroll
            for (int mf = 0; mf < 4; mf++)
#pragma unroll
                for (int nf = 0; nf < 8; nf++)
                    mma16816h(acc[mf][nf], aq[mf], &bq[(nf >> 1) * 4 + (nf & 1) * 2]);
        }
        __syncthreads();
    }

    const float* bias = args.bias[z];
    __half* Oh = args.Oh[z];
    const int mode = args.mode[z], part = args.part[z];

    const int g = lane >> 2, tq = lane & 3;
    float2 bv[8];
#pragma unroll
    for (int nf = 0; nf < 8; nf++)
        bv[nf] = *(const float2*)(bias + n0 + wn * 64 + nf * 8 + 2 * tq);

#pragma unroll
    for (int mf = 0; mf < 4; mf++) {
#pragma unroll
        for (int half = 0; half < 2; half++) {
            const int m = m0 + wm * 64 + mf * 16 + g + half * 8;
            const int bb = m >> 9, ll = m & 511;
#pragma unroll
            for (int nf = 0; nf < 8; nf++) {
                const int n = n0 + wn * 64 + nf * 8 + 2 * tq;
                const int h = n >> 6, dd = n & 63;
                float vx = acc[mf][nf][half * 2 + 0] + bv[nf].x;
                float vy = acc[mf][nf][half * 2 + 1] + bv[nf].y;
                __half hx = __float2half(vx), hy = __float2half(vy);
                if (mode == 0) {
                    size_t dst = ((((size_t)bb * NH_ + h) * L_ + ll) * DCAT)
                               + (size_t)part * 64 + dd;
                    __half2 hi2; hi2.x = hx; hi2.y = hy;
                    *(__half2*)(Oh + dst) = hi2;
                } else {
                    size_t dst = (((size_t)bb * NH_ + h) * HD_ + dd) * L_ + ll;
                    Oh[dst] = hx;
                    Oh[dst + L_] = hy;
                }
            }
        }
    }
}

// ---------------- output projection GEMM (known-good 256-thread core) ----------------
__global__ __launch_bounds__(256, 2)
void gemm_out(const __half* __restrict__ A, const __half* __restrict__ Bh,
              const float* __restrict__ bias, float* __restrict__ out)
{
    extern __shared__ char smem[];
    const uint32_t sbase = smem_u32(smem);
    const int tid = threadIdx.x;
    const int wid = tid >> 5, lane = tid & 31;
    const int m0 = blockIdx.y * 128, n0 = blockIdx.x * 128;
    const int wm = wid & 3, wn = wid >> 2;

    float acc[2][8][4];
#pragma unroll
    for (int mf = 0; mf < 2; mf++)
#pragma unroll
        for (int nf = 0; nf < 8; nf++)
#pragma unroll
            for (int q = 0; q < 4; q++) acc[mf][nf][q] = 0.f;

    const uint32_t a_l = (uint32_t)(wm * 32 + (lane & 7) + ((lane >> 3) & 1) * 8) * ROWB
                       + (lane >> 4) * 16;
    const uint32_t b_l = (uint32_t)(wn * 64 + (lane & 7) + ((lane >> 4) & 1) * 8) * ROWB
                       + ((lane >> 3) & 1) * 16;

    load_tile_256(sbase, 0, 0, m0, n0, tid, A, Bh);
    load_tile_256(sbase, 1, 1, m0, n0, tid, A, Bh);

    for (int c = 0; c < NCHUNKW; c++) {
        if (c < NCHUNKW - 1) asm volatile("cp.async.wait_group 1;" ::: "memory");
        else                 asm volatile("cp.async.wait_group 0;" ::: "memory");
        __syncthreads();
        if (c + 2 < NCHUNKW)
            load_tile_256(sbase, (c + 2) % 3, c + 2, m0, n0, tid, A, Bh);

        const uint32_t sb = sbase + (uint32_t)(c % 3) * STAGE_B;
        const uint32_t aBase  = sb + a_l;
        const uint32_t bhBase = sb + ATILE_B + b_l;
#pragma unroll
        for (int kk = 0; kk < KC / 16; kk++) {
            const uint32_t koff = kk * 32;
            uint32_t aq[2][4];
#pragma unroll
            for (int mf = 0; mf < 2; mf++)
                ldm_x4(aq[mf], aBase + mf * 16 * ROWB + koff);
            uint32_t bq[16];
#pragma unroll
            for (int np = 0; np < 4; np++)
                ldm_x4(&bq[np * 4], bhBase + np * 16 * ROWB + koff);
#pragma unroll
            for (int mf = 0; mf < 2; mf++)
#pragma unroll
                for (int nf = 0; nf < 8; nf++)
                    mma16816h(acc[mf][nf], aq[mf], &bq[(nf >> 1) * 4 + (nf & 1) * 2]);
        }
        __syncthreads();
    }

    const int g = lane >> 2, tq = lane & 3;
    float2 bv[8];
#pragma unroll
    for (int nf = 0; nf < 8; nf++)
        bv[nf] = *(const float2*)(bias + n0 + wn * 64 + nf * 8 + 2 * tq);
#pragma unroll
    for (int mf = 0; mf < 2; mf++)
#pragma unroll
        for (int half = 0; half < 2; half++) {
            const int m = m0 + wm * 32 + mf * 16 + g + half * 8;
#pragma unroll
            for (int nf = 0; nf < 8; nf++) {
                const int n = n0 + wn * 64 + nf * 8 + 2 * tq;
                float2 v;
                v.x = acc[mf][nf][half * 2 + 0] + bv[nf].x;
                v.y = acc[mf][nf][half * 2 + 1] + bv[nf].y;
                *(float2*)(out + (size_t)m * HID_ + n) = v;
            }
        }
}

// ---------------- flash attention: fp16 QK+PV, double-buffered K/V tiles ----------------
#define AQ_STRIDE 400u
#define AV_STRIDE 144u
#define SM_Q    0u
#define KV_STG0 25600u
#define KV_STGB 34816u
#define ATT_SMEM (25600 + 2*34816)

__global__ __launch_bounds__(128, 2)
void attn_mma(const float* __restrict__ rel,
              const __half* __restrict__ Qf, const __half* __restrict__ Kf,
              const __half* __restrict__ Vtf,
              __half* __restrict__ Of)
{
    extern __shared__ char smc[];
    const uint32_t sb = smem_u32(smc);
    const int qt = (int)gridDim.x - 1 - (int)blockIdx.x;
    const int bh = blockIdx.y;
    const int q0 = qt * 64;
    const int tid = threadIdx.x, wid = tid >> 5, lane = tid & 31;
    const int g = lane >> 2, tq = lane & 3;
    const int wrow = wid * 16;

    const __half* qf_g = Qf  + (size_t)bh * L_ * DCAT;
    const __half* kf_g = Kf  + (size_t)bh * L_ * DCAT;
    const __half* vf_g = Vtf + (size_t)bh * HD_ * L_;
    const float* relg = rel + (size_t)bh * L_ * L_;

#pragma unroll
    for (int i = 0; i < 12; i++) {
        int idx = i * 128 + tid;
        int r = idx / 24, s2 = idx % 24;
        cp16(sb + SM_Q + r * AQ_STRIDE + s2 * 16,
             qf_g + (size_t)(q0 + r) * DCAT + s2 * 8);
    }
    asm volatile("cp.async.commit_group;");

    auto load_tile = [&](int kt, int s) {
        const int k0 = kt * 64;
        const uint32_t stg = sb + KV_STG0 + (uint32_t)s * KV_STGB;
#pragma unroll
        for (int i = 0; i < 16; i++) {
            int idx = i * 128 + tid;
            if (idx < 1536) {
                int r = idx / 24, s2 = idx % 24;
                cp16(stg + r * AQ_STRIDE + s2 * 16,
                     kf_g + (size_t)(k0 + r) * DCAT + s2 * 8);
            } else {
                int j = idx - 1536;
                int d = j >> 3, s2 = j & 7;
                cp16(stg + 25600u + d * AV_STRIDE + s2 * 16,
                     vf_g + (size_t)d * L_ + k0 + s2 * 8);
            }
        }
        asm volatile("cp.async.commit_group;");
    };

    const int ntiles = qt + 1;
    load_tile(0, 0);

    float m_i[2] = {-3.0e38f, -3.0e38f};
    float l_i[2] = {0.f, 0.f};
    float oacc[8][4];
#pragma unroll
    for (int nf = 0; nf < 8; nf++)
#pragma unroll
        for (int q = 0; q < 4; q++) oacc[nf][q] = 0.f;

    const uint32_t aoffQ = (uint32_t)(wrow + (lane & 7) + ((lane >> 3) & 1) * 8) * AQ_STRIDE
                         + (lane >> 4) * 16;
    const uint32_t boffK = (uint32_t)((lane & 7) + ((lane >> 4) & 1) * 8) * AQ_STRIDE
                         + ((lane >> 3) & 1) * 16;
    const uint32_t boffV = (uint32_t)((lane & 7) + ((lane >> 4) & 1) * 8) * AV_STRIDE
                         + ((lane >> 3) & 1) * 16;

    const int row0c = q0 + wrow + g;
    const int row1c = row0c + 8;

    for (int kt = 0; kt < ntiles; kt++) {
        const int k0 = kt * 64;
        if (kt + 1 < ntiles) load_tile(kt + 1, (kt + 1) & 1);
        if (kt + 1 < ntiles) asm volatile("cp.async.wait_group 1;" ::: "memory");
        else                 asm volatile("cp.async.wait_group 0;" ::: "memory");
        __syncthreads();

        const bool active = (k0 <= q0 + wrow + 15);
        if (active) {
            const uint32_t stg = sb + KV_STG0 + (uint32_t)(kt & 1) * KV_STGB;
            const uint32_t kBase = stg;
            const uint32_t vBase = stg + 25600u;

            float2 rr0[8], rr1[8];
#pragma unroll
            for (int nf = 0; nf < 8; nf++) {
                const int col = k0 + nf * 8 + 2 * tq;
                rr0[nf] = *(const float2*)(relg + (size_t)row0c * L_ + col);
                rr1[nf] = *(const float2*)(relg + (size_t)row1c * L_ + col);
            }

            float sacc[8][4];
#pragma unroll
            for (int nf = 0; nf < 8; nf++)
#pragma unroll
                for (int q = 0; q < 4; q++) sacc[nf][q] = 0.f;

#pragma unroll
            for (int ks = 0; ks < 12; ks++) {
                const uint32_t koff = ks * 32;
                uint32_t aq[4], bq[16];
                ldm_x4(aq, sb + SM_Q + aoffQ + koff);
#pragma unroll
                for (int np = 0; np < 4; np++)
                    ldm_x4(&bq[np * 4], kBase + boffK + np * 16 * AQ_STRIDE + koff);
#pragma unroll
                for (int nf = 0; nf < 8; nf++)
                    mma16816h(sacc[nf], aq, &bq[(nf >> 1) * 4 + (nf & 1) * 2]);
            }

            const int row0 = row0c;
            const int row1 = row1c;
            const bool diag = (k0 + 63 > q0 + wrow);
            float pmax0 = -3.0e38f, pmax1 = -3.0e38f;
#pragma unroll
            for (int nf = 0; nf < 8; nf++) {
                const int col = k0 + nf * 8 + 2 * tq;
                float s0 = fmaf(sacc[nf][0], 0.125f, rr0[nf].x);
                float s1 = fmaf(sacc[nf][1], 0.125f, rr0[nf].y);
                float s2 = fmaf(sacc[nf][2], 0.125f, rr1[nf].x);
                float s3 = fmaf(sacc[nf][3], 0.125f, rr1[nf].y);
                if (diag) {
                    if (col     > row0) s0 = -3.0e38f;
                    if (col + 1 > row0) s1 = -3.0e38f;
                    if (col     > row1) s2 = -3.0e38f;
                    if (col + 1 > row1) s3 = -3.0e38f;
                }
                sacc[nf][0] = s0; sacc[nf][1] = s1; sacc[nf][2] = s2; sacc[nf][3] = s3;
                pmax0 = fmaxf(pmax0, fmaxf(s0, s1));
                pmax1 = fmaxf(pmax1, fmaxf(s2, s3));
            }
            {
                __half2 hm = __floats2half2_rn(pmax0, pmax1);
#pragma unroll
                for (int d = 1; d < 4; d <<= 1) {
                    uint32_t u = *(uint32_t*)&hm;
                    uint32_t v = __shfl_xor_sync(0xffffffffu, u, d);
                    hm = __hmax2(hm, *(__half2*)&v);
                }
                float2 fm = __half22float2(hm);
                pmax0 = fm.x;  pmax1 = fm.y;
            }
            const float nm0 = fmaxf(m_i[0], pmax0);
            const float nm1 = fmaxf(m_i[1], pmax1);
            const float al0 = __expf(m_i[0] - nm0);
            const float al1 = __expf(m_i[1] - nm1);
            float rs0 = 0.f, rs1 = 0.f;
#pragma unroll
            for (int nf = 0; nf < 8; nf++) {
                sacc[nf][0] = __expf(sacc[nf][0] - nm0);
                sacc[nf][1] = __expf(sacc[nf][1] - nm0);
                sacc[nf][2] = __expf(sacc[nf][2] - nm1);
                sacc[nf][3] = __expf(sacc[nf][3] - nm1);
                rs0 += sacc[nf][0] + sacc[nf][1];
                rs1 += sacc[nf][2] + sacc[nf][3];
            }
#pragma unroll
            for (int d = 1; d < 4; d <<= 1) {
                rs0 += __shfl_xor_sync(0xffffffffu, rs0, d);
                rs1 += __shfl_xor_sync(0xffffffffu, rs1, d);
            }
            l_i[0] = l_i[0] * al0 + rs0;  m_i[0] = nm0;
            l_i[1] = l_i[1] * al1 + rs1;  m_i[1] = nm1;
#pragma unroll
            for (int nf = 0; nf < 8; nf++) {
                oacc[nf][0] *= al0; oacc[nf][1] *= al0;
                oacc[nf][2] *= al1; oacc[nf][3] *= al1;
            }

#pragma unroll
            for (int ks = 0; ks < 4; ks++) {
                uint32_t af[4];
                af[0] = pack_h2(sacc[2*ks][0],   sacc[2*ks][1]);
                af[1] = pack_h2(sacc[2*ks][2],   sacc[2*ks][3]);
                af[2] = pack_h2(sacc[2*ks+1][0], sacc[2*ks+1][1]);
                af[3] = pack_h2(sacc[2*ks+1][2], sacc[2*ks+1][3]);
                uint32_t bv[16];
                const uint32_t koff = ks * 32;
#pragma unroll
                for (int np = 0; np < 4; np++)
                    ldm_x4(&bv[np * 4], vBase + boffV + np * 16 * AV_STRIDE + koff);
#pragma unroll
                for (int nf = 0; nf < 8; nf++)
                    mma16816h(oacc[nf], af, &bv[(nf >> 1) * 4 + (nf & 1) * 2]);
            }
        }
        __syncthreads();
    }

    const int b = bh >> 4, h = bh & 15;
    const float inv0 = 1.0f / l_i[0];
    const float inv1 = 1.0f / l_i[1];
    const size_t m0g = (size_t)(b * L_ + q0 + wrow + g) * HID_;
    const size_t m1g = m0g + 8 * HID_;
#pragma unroll
    for (int nf = 0; nf < 8; nf++) {
        const int col = h * 64 + nf * 8 + 2 * tq;
        __half2 o0 = __floats2half2_rn(oacc[nf][0] * inv0, oacc[nf][1] * inv0);
        __half2 o1 = __floats2half2_rn(oacc[nf][2] * inv1, oacc[nf][3] * inv1);
        *(__half2*)(Of + m0g + col) = o0;
        *(__half2*)(Of + m1g + col) = o1;
    }
}

// ---------------- launcher ----------------
extern "C" void kernel_launch(void* const* d_in, const int* in_sizes, int n_in,
                              void* d_out, int out_size)
{
    const float* rel = (const float*)d_in[5];
    float* out = (float*)d_out;

    __half *xf, *wfh, *qf, *kf, *vf;
    cudaGetSymbolAddress((void**)&xf, g_xf);
    cudaGetSymbolAddress((void**)&wfh, g_wfh);
    cudaGetSymbolAddress((void**)&qf, g_qf);
    cudaGetSymbolAddress((void**)&kf, g_kf);
    cudaGetSymbolAddress((void**)&vf, g_vf);

    cudaFuncSetAttribute(gemm_batch, cudaFuncAttributeMaxDynamicSharedMemorySize, GEMM_SMEM);
    cudaFuncSetAttribute(gemm_out, cudaFuncAttributeMaxDynamicSharedMemorySize, GEMM_SMEM);
    cudaFuncSetAttribute(attn_mma, cudaFuncAttributeMaxDynamicSharedMemorySize, ATT_SMEM);

    const int n4 = (int)(XN / 4);

    SplitSrc ss;
    ss.p[0] = (const float*)d_in[0];
    ss.p[1] = (const float*)d_in[1];
    ss.p[2] = (const float*)d_in[2];
    ss.p[3] = (const float*)d_in[3];
    split_f16<<<dim3((n4 + 255) / 256, 4), 256>>>(ss, xf, n4);

    WSrc ws;
    ws.p[0] = (const float*)d_in[6];   ws.p[1] = (const float*)d_in[8];
    ws.p[2] = (const float*)d_in[10];  ws.p[3] = (const float*)d_in[12];
    ws.p[4] = (const float*)d_in[14];  ws.p[5] = (const float*)d_in[16];
    ws.p[6] = (const float*)d_in[18];  ws.p[7] = (const float*)d_in[20];
    splitT_h<<<dim3(32, 32, 8), dim3(32, 8)>>>(ws, wfh);

    GemmB gb;
    const int ain[7]  = {0, 1, 2, 0, 1, 2, 3};
    const int wsl[7]  = {0, 3, 5, 1, 4, 6, 2};
    const int bidx[7] = {7, 13, 17, 9, 15, 19, 11};
    for (int z = 0; z < 7; z++) {
        gb.A[z]  = xf + (size_t)ain[z] * XN;
        gb.Bh[z] = wfh + (size_t)wsl[z] * WN;
        gb.bias[z] = (const float*)d_in[bidx[z]];
    }
    gb.Oh[0] = qf; gb.mode[0] = 0; gb.part[0] = 0;
    gb.Oh[1] = qf; gb.mode[1] = 0; gb.part[1] = 1;
    gb.Oh[2] = qf; gb.mode[2] = 0; gb.part[2] = 2;
    gb.Oh[3] = kf; gb.mode[3] = 0; gb.part[3] = 0;
    gb.Oh[4] = kf; gb.mode[4] = 0; gb.part[4] = 1;
    gb.Oh[5] = kf; gb.mode[5] = 0; gb.part[5] = 2;
    gb.Oh[6] = vf; gb.mode[6] = 2; gb.part[6] = 0;
    gemm_batch<<<dim3(8, 64, 7), 128, GEMM_SMEM>>>(gb);

    attn_mma<<<dim3(8, 256), 128, ATT_SMEM>>>(rel, qf, kf, vf, xf + 4 * XN);

    gemm_out<<<dim3(8, 64), 256, GEMM_SMEM>>>(xf + 4 * XN, wfh + 7 * WN,
                                              (const float*)d_in[21], out);
}

// round 17
// speedup vs baseline: 1.0159x; 1.0159x over previous
#include <cuda_runtime.h>
#include <cuda_bf16.h>
#include <cuda_fp16.h>
#include <cstdint>

#define B_    16
#define L_    512
#define HID_  1024
#define NH_   16
#define HD_   64
#define M_TOT (B_*L_)      // 8192
#define DCAT  192
#define XN    ((size_t)M_TOT*HID_)
#define WN    ((size_t)HID_*HID_)

// ---------------- scratch (static device arrays) ----------------
__device__ __half g_xf[5ULL*XN];            // fp16 activations: 4 inputs + attn-out
__device__ __half g_wfh[8ULL*WN];           // W^T fp16
__device__ __half g_qf [(size_t)B_*NH_*L_*DCAT];   // Q fp16
__device__ __half g_kf [(size_t)B_*NH_*L_*DCAT];   // K fp16
__device__ __half g_vf [(size_t)B_*NH_*HD_*L_];    // Vt fp16

// ---------------- PTX helpers (baseline ISA only) ----------------
__device__ __forceinline__ uint32_t smem_u32(const void* p) {
    uint32_t a;
    asm("{ .reg .u64 t; cvta.to.shared.u64 t, %1; cvt.u32.u64 %0, t; }" : "=r"(a) : "l"(p));
    return a;
}
__device__ __forceinline__ void cp16(uint32_t dst, const void* src) {
    asm volatile("cp.async.cg.shared.global [%0], [%1], 16;" :: "r"(dst), "l"(src));
}
__device__ __forceinline__ void ldm_x4(uint32_t* r, uint32_t addr) {
    asm volatile("ldmatrix.sync.aligned.m8n8.x4.shared.b16 {%0,%1,%2,%3}, [%4];"
                 : "=r"(r[0]), "=r"(r[1]), "=r"(r[2]), "=r"(r[3]) : "r"(addr));
}
__device__ __forceinline__ void mma16816h(float* d, const uint32_t* a, const uint32_t* b) {
    asm volatile(
        "mma.sync.aligned.m16n8k16.row.col.f32.f16.f16.f32 "
        "{%0,%1,%2,%3}, {%4,%5,%6,%7}, {%8,%9}, {%0,%1,%2,%3};"
        : "+f"(d[0]), "+f"(d[1]), "+f"(d[2]), "+f"(d[3])
        : "r"(a[0]), "r"(a[1]), "r"(a[2]), "r"(a[3]), "r"(b[0]), "r"(b[1]));
}
__device__ __forceinline__ uint32_t pack_h2(float a, float b) {
    __half2 t = __floats2half2_rn(a, b);
    return *(uint32_t*)&t;
}

// ---------------- batched fp32 -> fp16 ----------------
struct SplitSrc { const float* p[4]; };
__global__ __launch_bounds__(256)
void split_f16(SplitSrc s, __half* __restrict__ dst, int n4)
{
    int i = blockIdx.x * 256 + threadIdx.x;
    if (i >= n4) return;
    int z = blockIdx.y;
    const float* src = s.p[z];
    __half* dz = dst + (size_t)z * XN;
    float4 v = ((const float4*)src)[i];
    __half2 a = __floats2half2_rn(v.x, v.y);
    __half2 b = __floats2half2_rn(v.z, v.w);
    ((__half2*)dz)[i*2]   = a;
    ((__half2*)dz)[i*2+1] = b;
}

// ---------------- batched W[k][n] -> W^T[n][k] fp16 ----------------
struct WSrc { const float* p[8]; };
__global__ __launch_bounds__(256)
void splitT_h(WSrc s, __half* __restrict__ hiT)
{
    __shared__ float t[32][33];
    int z = blockIdx.z;
    const float* W = s.p[z];
    __half* hz = hiT + (size_t)z * WN;
    int bx = blockIdx.x * 32, by = blockIdx.y * 32;
    int tx = threadIdx.x, ty = threadIdx.y;
#pragma unroll
    for (int j = 0; j < 4; j++)
        t[ty + 8*j][tx] = W[(size_t)(by + ty + 8*j) * HID_ + bx + tx];
    __syncthreads();
#pragma unroll
    for (int j = 0; j < 4; j++) {
        float v = t[tx][ty + 8*j];
        int n = bx + ty + 8*j, k = by + tx;
        hz[(size_t)n * HID_ + k] = __float2half(v);
    }
}

// ---------------- GEMM core: single-product, CTA 128x128, 3-stage, 256 thr ----------------
#define KC        64
#define NCHUNKW   16
#define ROWB      144u
#define ATILE_B   (128u*ROWB)            // 18432
#define STAGE_B   (2u*ATILE_B)           // 36864 (A + B)
#define GEMM_SMEM (3*STAGE_B)            // 110592 -> occ 2

__device__ __forceinline__ void gemm_load_tile(
    uint32_t sbase, int stage, int c, int m0, int n0, int tid,
    const __half* A, const __half* Bh)
{
    const int k0 = c * KC;
    const uint32_t dstA = sbase + (uint32_t)stage * STAGE_B;
#pragma unroll
    for (int i = 0; i < 8; i++) {
        int idx = i * 256 + tid;
        int r = (idx >> 3) & 127, c16 = idx & 7;
        if (idx < 1024)
            cp16(dstA + r * ROWB + c16 * 16,
                 A + (size_t)(m0 + r) * HID_ + k0 + c16 * 8);
        else
            cp16(dstA + ATILE_B + r * ROWB + c16 * 16,
                 Bh + (size_t)(n0 + r) * HID_ + k0 + c16 * 8);
    }
    asm volatile("cp.async.commit_group;");
}

__device__ __forceinline__ void gemm_core(
    uint32_t sbase, int m0, int n0, int tid, int wm, int wn, int lane,
    const __half* A, const __half* Bh,
    float acc[2][8][4])
{
    const uint32_t a_l = (uint32_t)(wm * 32 + (lane & 7) + ((lane >> 3) & 1) * 8) * ROWB
                       + (lane >> 4) * 16;
    const uint32_t b_l = (uint32_t)(wn * 64 + (lane & 7) + ((lane >> 4) & 1) * 8) * ROWB
                       + ((lane >> 3) & 1) * 16;

    gemm_load_tile(sbase, 0, 0, m0, n0, tid, A, Bh);
    gemm_load_tile(sbase, 1, 1, m0, n0, tid, A, Bh);

    for (int c = 0; c < NCHUNKW; c++) {
        if (c < NCHUNKW - 1) asm volatile("cp.async.wait_group 1;" ::: "memory");
        else                 asm volatile("cp.async.wait_group 0;" ::: "memory");
        __syncthreads();
        // NOTE: no trailing sync needed — stage (c+2)%3 was last read in
        // iteration c-1, and every warp passed THIS barrier only after
        // finishing iteration c-1's reads.
        if (c + 2 < NCHUNKW)
            gemm_load_tile(sbase, (c + 2) % 3, c + 2, m0, n0, tid, A, Bh);

        const uint32_t sb = sbase + (uint32_t)(c % 3) * STAGE_B;
        const uint32_t aBase  = sb + a_l;
        const uint32_t bhBase = sb + ATILE_B + b_l;
#pragma unroll
        for (int kk = 0; kk < KC / 16; kk++) {
            const uint32_t koff = kk * 32;
            uint32_t aq[2][4];
#pragma unroll
            for (int mf = 0; mf < 2; mf++)
                ldm_x4(aq[mf], aBase + mf * 16 * ROWB + koff);
            uint32_t bq[16];
#pragma unroll
            for (int np = 0; np < 4; np++)
                ldm_x4(&bq[np * 4], bhBase + np * 16 * ROWB + koff);
#pragma unroll
            for (int mf = 0; mf < 2; mf++)
#pragma unroll
                for (int nf = 0; nf < 8; nf++)
                    mma16816h(acc[mf][nf], aq[mf], &bq[(nf >> 1) * 4 + (nf & 1) * 2]);
        }
    }
}

// ---------------- batched projection GEMMs ----------------
// mode 0: scatter [bh][l][192] (Q and K); mode 2: V transpose [bh][d][l]
struct GemmB {
    const __half *A[7], *Bh[7];
    const float* bias[7];
    __half *Oh[7];
    int mode[7];
    int part[7];
};

__global__ __launch_bounds__(256, 2)
void gemm_batch(GemmB args)
{
    extern __shared__ char smem[];
    const uint32_t sbase = smem_u32(smem);
    const int z = blockIdx.z;
    const int tid = threadIdx.x;
    const int wid = tid >> 5, lane = tid & 31;
    const int m0 = blockIdx.y * 128, n0 = blockIdx.x * 128;
    const int wm = wid & 3, wn = wid >> 2;

    float acc[2][8][4];
#pragma unroll
    for (int mf = 0; mf < 2; mf++)
#pragma unroll
        for (int nf = 0; nf < 8; nf++)
#pragma unroll
            for (int q = 0; q < 4; q++) acc[mf][nf][q] = 0.f;

    gemm_core(sbase, m0, n0, tid, wm, wn, lane, args.A[z], args.Bh[z], acc);

    const float* bias = args.bias[z];
    __half* Oh = args.Oh[z];
    const int mode = args.mode[z], part = args.part[z];

    const int g = lane >> 2, tq = lane & 3;
    float2 bv[8];
#pragma unroll
    for (int nf = 0; nf < 8; nf++)
        bv[nf] = *(const float2*)(bias + n0 + wn * 64 + nf * 8 + 2 * tq);

#pragma unroll
    for (int mf = 0; mf < 2; mf++) {
#pragma unroll
        for (int half = 0; half < 2; half++) {
            const int m = m0 + wm * 32 + mf * 16 + g + half * 8;
            const int bb = m >> 9, ll = m & 511;
#pragma unroll
            for (int nf = 0; nf < 8; nf++) {
                const int n = n0 + wn * 64 + nf * 8 + 2 * tq;
                const int h = n >> 6, dd = n & 63;
                float vx = acc[mf][nf][half * 2 + 0] + bv[nf].x;
                float vy = acc[mf][nf][half * 2 + 1] + bv[nf].y;
                __half hx = __float2half(vx), hy = __float2half(vy);
                if (mode == 0) {
                    size_t dst = ((((size_t)bb * NH_ + h) * L_ + ll) * DCAT)
                               + (size_t)part * 64 + dd;
                    __half2 hi2; hi2.x = hx; hi2.y = hy;
                    *(__half2*)(Oh + dst) = hi2;
                } else {
                    size_t dst = (((size_t)bb * NH_ + h) * HD_ + dd) * L_ + ll;
                    Oh[dst] = hx;
                    Oh[dst + L_] = hy;
                }
            }
        }
    }
}

// ---------------- output projection GEMM (fp32 out) ----------------
__global__ __launch_bounds__(256, 2)
void gemm_out(const __half* __restrict__ A, const __half* __restrict__ Bh,
              const float* __restrict__ bias, float* __restrict__ out)
{
    extern __shared__ char smem[];
    const uint32_t sbase = smem_u32(smem);
    const int tid = threadIdx.x;
    const int wid = tid >> 5, lane = tid & 31;
    const int m0 = blockIdx.y * 128, n0 = blockIdx.x * 128;
    const int wm = wid & 3, wn = wid >> 2;

    float acc[2][8][4];
#pragma unroll
    for (int mf = 0; mf < 2; mf++)
#pragma unroll
        for (int nf = 0; nf < 8; nf++)
#pragma unroll
            for (int q = 0; q < 4; q++) acc[mf][nf][q] = 0.f;

    gemm_core(sbase, m0, n0, tid, wm, wn, lane, A, Bh, acc);

    const int g = lane >> 2, tq = lane & 3;
    float2 bv[8];
#pragma unroll
    for (int nf = 0; nf < 8; nf++)
        bv[nf] = *(const float2*)(bias + n0 + wn * 64 + nf * 8 + 2 * tq);
#pragma unroll
    for (int mf = 0; mf < 2; mf++)
#pragma unroll
        for (int half = 0; half < 2; half++) {
            const int m = m0 + wm * 32 + mf * 16 + g + half * 8;
#pragma unroll
            for (int nf = 0; nf < 8; nf++) {
                const int n = n0 + wn * 64 + nf * 8 + 2 * tq;
                float2 v;
                v.x = acc[mf][nf][half * 2 + 0] + bv[nf].x;
                v.y = acc[mf][nf][half * 2 + 1] + bv[nf].y;
                *(float2*)(out + (size_t)m * HID_ + n) = v;
            }
        }
}

// ---------------- flash attention: fp16 QK+PV, double-buffered K/V (R15) ----------------
#define AQ_STRIDE 400u
#define AV_STRIDE 144u
#define SM_Q    0u
#define KV_STG0 25600u
#define KV_STGB 34816u
#define ATT_SMEM (25600 + 2*34816)

__global__ __launch_bounds__(128, 2)
void attn_mma(const float* __restrict__ rel,
              const __half* __restrict__ Qf, const __half* __restrict__ Kf,
              const __half* __restrict__ Vtf,
              __half* __restrict__ Of)
{
    extern __shared__ char smc[];
    const uint32_t sb = smem_u32(smc);
    const int qt = (int)gridDim.x - 1 - (int)blockIdx.x;
    const int bh = blockIdx.y;
    const int q0 = qt * 64;
    const int tid = threadIdx.x, wid = tid >> 5, lane = tid & 31;
    const int g = lane >> 2, tq = lane & 3;
    const int wrow = wid * 16;

    const __half* qf_g = Qf  + (size_t)bh * L_ * DCAT;
    const __half* kf_g = Kf  + (size_t)bh * L_ * DCAT;
    const __half* vf_g = Vtf + (size_t)bh * HD_ * L_;
    const float* relg = rel + (size_t)bh * L_ * L_;

#pragma unroll
    for (int i = 0; i < 12; i++) {
        int idx = i * 128 + tid;
        int r = idx / 24, s2 = idx % 24;
        cp16(sb + SM_Q + r * AQ_STRIDE + s2 * 16,
             qf_g + (size_t)(q0 + r) * DCAT + s2 * 8);
    }
    asm volatile("cp.async.commit_group;");

    auto load_tile = [&](int kt, int s) {
        const int k0 = kt * 64;
        const uint32_t stg = sb + KV_STG0 + (uint32_t)s * KV_STGB;
#pragma unroll
        for (int i = 0; i < 16; i++) {
            int idx = i * 128 + tid;
            if (idx < 1536) {
                int r = idx / 24, s2 = idx % 24;
                cp16(stg + r * AQ_STRIDE + s2 * 16,
                     kf_g + (size_t)(k0 + r) * DCAT + s2 * 8);
            } else {
                int j = idx - 1536;
                int d = j >> 3, s2 = j & 7;
                cp16(stg + 25600u + d * AV_STRIDE + s2 * 16,
                     vf_g + (size_t)d * L_ + k0 + s2 * 8);
            }
        }
        asm volatile("cp.async.commit_group;");
    };

    const int ntiles = qt + 1;
    load_tile(0, 0);

    float m_i[2] = {-3.0e38f, -3.0e38f};
    float l_i[2] = {0.f, 0.f};
    float oacc[8][4];
#pragma unroll
    for (int nf = 0; nf < 8; nf++)
#pragma unroll
        for (int q = 0; q < 4; q++) oacc[nf][q] = 0.f;

    const uint32_t aoffQ = (uint32_t)(wrow + (lane & 7) + ((lane >> 3) & 1) * 8) * AQ_STRIDE
                         + (lane >> 4) * 16;
    const uint32_t boffK = (uint32_t)((lane & 7) + ((lane >> 4) & 1) * 8) * AQ_STRIDE
                         + ((lane >> 3) & 1) * 16;
    const uint32_t boffV = (uint32_t)((lane & 7) + ((lane >> 4) & 1) * 8) * AV_STRIDE
                         + ((lane >> 3) & 1) * 16;

    const int row0c = q0 + wrow + g;
    const int row1c = row0c + 8;

    for (int kt = 0; kt < ntiles; kt++) {
        const int k0 = kt * 64;
        if (kt + 1 < ntiles) load_tile(kt + 1, (kt + 1) & 1);
        if (kt + 1 < ntiles) asm volatile("cp.async.wait_group 1;" ::: "memory");
        else                 asm volatile("cp.async.wait_group 0;" ::: "memory");
        __syncthreads();

        const bool active = (k0 <= q0 + wrow + 15);
        if (active) {
            const uint32_t stg = sb + KV_STG0 + (uint32_t)(kt & 1) * KV_STGB;
            const uint32_t kBase = stg;
            const uint32_t vBase = stg + 25600u;

            float2 rr0[8], rr1[8];
#pragma unroll
            for (int nf = 0; nf < 8; nf++) {
                const int col = k0 + nf * 8 + 2 * tq;
                rr0[nf] = *(const float2*)(relg + (size_t)row0c * L_ + col);
                rr1[nf] = *(const float2*)(relg + (size_t)row1c * L_ + col);
            }

            float sacc[8][4];
#pragma unroll
            for (int nf = 0; nf < 8; nf++)
#pragma unroll
                for (int q = 0; q < 4; q++) sacc[nf][q] = 0.f;

#pragma unroll
            for (int ks = 0; ks < 12; ks++) {
                const uint32_t koff = ks * 32;
                uint32_t aq[4], bq[16];
                ldm_x4(aq, sb + SM_Q + aoffQ + koff);
#pragma unroll
                for (int np = 0; np < 4; np++)
                    ldm_x4(&bq[np * 4], kBase + boffK + np * 16 * AQ_STRIDE + koff);
#pragma unroll
                for (int nf = 0; nf < 8; nf++)
                    mma16816h(sacc[nf], aq, &bq[(nf >> 1) * 4 + (nf & 1) * 2]);
            }

            const int row0 = row0c;
            const int row1 = row1c;
            const bool diag = (k0 + 63 > q0 + wrow);
            float pmax0 = -3.0e38f, pmax1 = -3.0e38f;
#pragma unroll
            for (int nf = 0; nf < 8; nf++) {
                const int col = k0 + nf * 8 + 2 * tq;
                float s0 = fmaf(sacc[nf][0], 0.125f, rr0[nf].x);
                float s1 = fmaf(sacc[nf][1], 0.125f, rr0[nf].y);
                float s2 = fmaf(sacc[nf][2], 0.125f, rr1[nf].x);
                float s3 = fmaf(sacc[nf][3], 0.125f, rr1[nf].y);
                if (diag) {
                    if (col     > row0) s0 = -3.0e38f;
                    if (col + 1 > row0) s1 = -3.0e38f;
                    if (col     > row1) s2 = -3.0e38f;
                    if (col + 1 > row1) s3 = -3.0e38f;
                }
                sacc[nf][0] = s0; sacc[nf][1] = s1; sacc[nf][2] = s2; sacc[nf][3] = s3;
                pmax0 = fmaxf(pmax0, fmaxf(s0, s1));
                pmax1 = fmaxf(pmax1, fmaxf(s2, s3));
            }
            {
                __half2 hm = __floats2half2_rn(pmax0, pmax1);
#pragma unroll
                for (int d = 1; d < 4; d <<= 1) {
                    uint32_t u = *(uint32_t*)&hm;
                    uint32_t v = __shfl_xor_sync(0xffffffffu, u, d);
                    hm = __hmax2(hm, *(__half2*)&v);
                }
                float2 fm = __half22float2(hm);
                pmax0 = fm.x;  pmax1 = fm.y;
            }
            const float nm0 = fmaxf(m_i[0], pmax0);
            const float nm1 = fmaxf(m_i[1], pmax1);
            const float al0 = __expf(m_i[0] - nm0);
            const float al1 = __expf(m_i[1] - nm1);
            float rs0 = 0.f, rs1 = 0.f;
#pragma unroll
            for (int nf = 0; nf < 8; nf++) {
                sacc[nf][0] = __expf(sacc[nf][0] - nm0);
                sacc[nf][1] = __expf(sacc[nf][1] - nm0);
                sacc[nf][2] = __expf(sacc[nf][2] - nm1);
                sacc[nf][3] = __expf(sacc[nf][3] - nm1);
                rs0 += sacc[nf][0] + sacc[nf][1];
                rs1 += sacc[nf][2] + sacc[nf][3];
            }
#pragma unroll
            for (int d = 1; d < 4; d <<= 1) {
                rs0 += __shfl_xor_sync(0xffffffffu, rs0, d);
                rs1 += __shfl_xor_sync(0xffffffffu, rs1, d);
            }
            l_i[0] = l_i[0] * al0 + rs0;  m_i[0] = nm0;
            l_i[1] = l_i[1] * al1 + rs1;  m_i[1] = nm1;
#pragma unroll
            for (int nf = 0; nf < 8; nf++) {
                oacc[nf][0] *= al0; oacc[nf][1] *= al0;
                oacc[nf][2] *= al1; oacc[nf][3] *= al1;
            }

#pragma unroll
            for (int ks = 0; ks < 4; ks++) {
                uint32_t af[4];
                af[0] = pack_h2(sacc[2*ks][0],   sacc[2*ks][1]);
                af[1] = pack_h2(sacc[2*ks][2],   sacc[2*ks][3]);
                af[2] = pack_h2(sacc[2*ks+1][0], sacc[2*ks+1][1]);
                af[3] = pack_h2(sacc[2*ks+1][2], sacc[2*ks+1][3]);
                uint32_t bv[16];
                const uint32_t koff = ks * 32;
#pragma unroll
                for (int np = 0; np < 4; np++)
                    ldm_x4(&bv[np * 4], vBase + boffV + np * 16 * AV_STRIDE + koff);
#pragma unroll
                for (int nf = 0; nf < 8; nf++)
                    mma16816h(oacc[nf], af, &bv[(nf >> 1) * 4 + (nf & 1) * 2]);
            }
        }
        __syncthreads();   // required: next tile's load is issued pre-barrier
    }

    const int b = bh >> 4, h = bh & 15;
    const float inv0 = 1.0f / l_i[0];
    const float inv1 = 1.0f / l_i[1];
    const size_t m0g = (size_t)(b * L_ + q0 + wrow + g) * HID_;
    const size_t m1g = m0g + 8 * HID_;
#pragma unroll
    for (int nf = 0; nf < 8; nf++) {
        const int col = h * 64 + nf * 8 + 2 * tq;
        __half2 o0 = __floats2half2_rn(oacc[nf][0] * inv0, oacc[nf][1] * inv0);
        __half2 o1 = __floats2half2_rn(oacc[nf][2] * inv1, oacc[nf][3] * inv1);
        *(__half2*)(Of + m0g + col) = o0;
        *(__half2*)(Of + m1g + col) = o1;
    }
}

// ---------------- launcher ----------------
extern "C" void kernel_launch(void* const* d_in, const int* in_sizes, int n_in,
                              void* d_out, int out_size)
{
    const float* rel = (const float*)d_in[5];
    float* out = (float*)d_out;

    __half *xf, *wfh, *qf, *kf, *vf;
    cudaGetSymbolAddress((void**)&xf, g_xf);
    cudaGetSymbolAddress((void**)&wfh, g_wfh);
    cudaGetSymbolAddress((void**)&qf, g_qf);
    cudaGetSymbolAddress((void**)&kf, g_kf);
    cudaGetSymbolAddress((void**)&vf, g_vf);

    cudaFuncSetAttribute(gemm_batch, cudaFuncAttributeMaxDynamicSharedMemorySize, GEMM_SMEM);
    cudaFuncSetAttribute(gemm_out, cudaFuncAttributeMaxDynamicSharedMemorySize, GEMM_SMEM);
    cudaFuncSetAttribute(attn_mma, cudaFuncAttributeMaxDynamicSharedMemorySize, ATT_SMEM);

    const int n4 = (int)(XN / 4);

    SplitSrc ss;
    ss.p[0] = (const float*)d_in[0];
    ss.p[1] = (const float*)d_in[1];
    ss.p[2] = (const float*)d_in[2];
    ss.p[3] = (const float*)d_in[3];
    split_f16<<<dim3((n4 + 255) / 256, 4), 256>>>(ss, xf, n4);

    WSrc ws;
    ws.p[0] = (const float*)d_in[6];   ws.p[1] = (const float*)d_in[8];
    ws.p[2] = (const float*)d_in[10];  ws.p[3] = (const float*)d_in[12];
    ws.p[4] = (const float*)d_in[14];  ws.p[5] = (const float*)d_in[16];
    ws.p[6] = (const float*)d_in[18];  ws.p[7] = (const float*)d_in[20];
    splitT_h<<<dim3(32, 32, 8), dim3(32, 8)>>>(ws, wfh);

    GemmB gb;
    const int ain[7]  = {0, 1, 2, 0, 1, 2, 3};
    const int wsl[7]  = {0, 3, 5, 1, 4, 6, 2};
    const int bidx[7] = {7, 13, 17, 9, 15, 19, 11};
    for (int z = 0; z < 7; z++) {
        gb.A[z]  = xf + (size_t)ain[z] * XN;
        gb.Bh[z] = wfh + (size_t)wsl[z] * WN;
        gb.bias[z] = (const float*)d_in[bidx[z]];
    }
    gb.Oh[0] = qf; gb.mode[0] = 0; gb.part[0] = 0;
    gb.Oh[1] = qf; gb.mode[1] = 0; gb.part[1] = 1;
    gb.Oh[2] = qf; gb.mode[2] = 0; gb.part[2] = 2;
    gb.Oh[3] = kf; gb.mode[3] = 0; gb.part[3] = 0;
    gb.Oh[4] = kf; gb.mode[4] = 0; gb.part[4] = 1;
    gb.Oh[5] = kf; gb.mode[5] = 0; gb.part[5] = 2;
    gb.Oh[6] = vf; gb.mode[6] = 2; gb.part[6] = 0;
    gemm_batch<<<dim3(8, 64, 7), 256, GEMM_SMEM>>>(gb);

    attn_mma<<<dim3(8, 256), 128, ATT_SMEM>>>(rel, qf, kf, vf, xf + 4 * XN);

    gemm_out<<<dim3(8, 64), 256, GEMM_SMEM>>>(xf + 4 * XN, wfh + 7 * WN,
                                              (const float*)d_in[21], out);
}